// round 11
// baseline (speedup 1.0000x reference)
#include <cuda_runtime.h>
#include <cuda_bf16.h>

// BinaryLutLayer: out[i] = (float)(int8) round_half_even( luts_float[i][addr_i] + 0.5 )
// addr_i = sum_b ((x[i][b] != 0) << b); N = 16384 rows, 14 bits, LUT row = 16384 floats.
//
// CONVERGED at the harness replay floor: four structural variants all time
// 6.62-6.66 us (two timer quanta) while ncu kernel time jitters 7.5-8.3 us
// under forced cache flush. Warm-run work is ~0.3 us (x + fixed-address LUT
// lines L2-resident across graph replays); the rest is fixed per-replay
// launch/wave-ramp overhead. All pipes idle (issue <2%, DRAM ~5%).
//
// This variant is the final unprobed structural point: 2 rows/thread.
// Row pairs start at 112 B = 7x16 B boundaries, so two rows of x load as
// 7 x LDG.128 (16B-aligned), 8192 threads / 64 CTAs, two independent
// dependent-gathers per thread, one STG.64. Expected flat vs R10.
//
// Correctness: int8 quantization recomputed from luts_float (d_in[1], fp32)
// since d_in[2]'s device dtype after the harness widened jnp.int8 is
// unknown. rintf == jnp.round (round-half-even) on bit-identical fp32 ->
// exact (rel_err = 0.0 in every passing round).

#define NUM_BITS 14
#define LUT_SIZE 16384
#define N_OUT    16384
#define TPB      128
#define ROWS_PER_THREAD 2

__global__ __launch_bounds__(TPB)
void binary_lut_kernel(const float* __restrict__ x,
                       const float* __restrict__ luts_float,
                       float* __restrict__ out)
{
    const int pair = blockIdx.x * TPB + threadIdx.x;    // row pair index
    const int row0 = pair * ROWS_PER_THREAD;            // first of 2 rows

    // 2 rows x 14 floats = 28 floats = 7 x float4, 16B-aligned
    // (pair * 112 bytes). All 7 loads independent -> one memory round-trip.
    const float4* __restrict__ p =
        (const float4*)(x + (size_t)row0 * NUM_BITS);

    float4 v[7];
    #pragma unroll
    for (int j = 0; j < 7; j++)
        v[j] = __ldg(&p[j]);

    // Unpack 28 lanes: bits 0..13 -> row0 address, bits 14..27 -> row1.
    const float* f = (const float*)v;   // 28 contiguous floats in registers
    int a0 = 0, a1 = 0;
    #pragma unroll
    for (int b = 0; b < NUM_BITS; b++) {
        a0 |= (f[b] != 0.0f)            ? (1 << b) : 0;
        a1 |= (f[NUM_BITS + b] != 0.0f) ? (1 << b) : 0;
    }

    // Two independent dependent gathers (row stride = 64 KB in the float LUT).
    const float lv0 = __ldg(luts_float + (size_t)row0 * LUT_SIZE + a0);
    const float lv1 = __ldg(luts_float + ((size_t)row0 + 1) * LUT_SIZE + a1);

    // round-half-even (== jnp.round) on bit-identical fp32, int8 cast, float.
    float2 o;
    o.x = (float)(signed char)rintf(lv0 + 0.5f);
    o.y = (float)(signed char)rintf(lv1 + 0.5f);
    *(float2*)(out + row0) = o;   // 8B-aligned (row0 even)
}

extern "C" void kernel_launch(void* const* d_in, const int* in_sizes, int n_in,
                              void* d_out, int out_size)
{
    const float* x          = (const float*)d_in[0];
    const float* luts_float = (const float*)d_in[1];
    // d_in[2] (luts_int) unused: device dtype after harness widening is
    // ambiguous; values are reproduced bit-exactly from luts_float.
    float* out = (float*)d_out;

    binary_lut_kernel<<<N_OUT / (TPB * ROWS_PER_THREAD), TPB>>>(x, luts_float, out);
}